// round 6
// baseline (speedup 1.0000x reference)
#include <cuda_runtime.h>
#include <math.h>

#define Bb 4
#define Cc 256
#define Nn 4096
#define Mm 4096
#define Hh 4
#define Dd 64
#define PT 68   // padded pitch for Vs/Pt smem tiles

// Scratch (allocation-free rule: __device__ globals)
__device__ float g_Q[Bb * Cc * Nn];
__device__ float g_K[Bb * Cc * Mm];
__device__ float g_V[Bb * Cc * Mm];
__device__ float g_O[Bb * Cc * Nn];

// ---------------------------------------------------------------------------
// Pointwise-conv projection: out[b][o][l] = sum_c W[o][c] * x[b][c][l] + bias[o]
// Tiled GEMM: 64x64 output tile, K-step 16, 256 threads, 4x4 microtile.
// grid: (L/64, Cc/64, Bb)
// ---------------------------------------------------------------------------
__global__ __launch_bounds__(256) void proj_kernel(
    const float* __restrict__ W, const float* __restrict__ bias,
    const float* __restrict__ x, float* __restrict__ out, int L)
{
    __shared__ float sW[16][64];   // [k][o]
    __shared__ float sX[16][64];   // [k][l]

    const int tid = threadIdx.x;
    const int l0 = blockIdx.x * 64;
    const int o0 = blockIdx.y * 64;
    const int b  = blockIdx.z;
    const float* xb = x + (size_t)b * Cc * L;

    const int ty = tid >> 4, tx = tid & 15;
    const int wo = tid >> 2, wk = (tid & 3) * 4;   // W-load mapping
    const int xk = tid >> 4, xl = (tid & 15) * 4;  // X-load mapping

    float acc[4][4] = {};

    for (int k0 = 0; k0 < Cc; k0 += 16) {
        float4 w4 = *(const float4*)&W[(size_t)(o0 + wo) * Cc + k0 + wk];
        sW[wk + 0][wo] = w4.x;
        sW[wk + 1][wo] = w4.y;
        sW[wk + 2][wo] = w4.z;
        sW[wk + 3][wo] = w4.w;
        *(float4*)&sX[xk][xl] =
            *(const float4*)&xb[(size_t)(k0 + xk) * L + l0 + xl];
        __syncthreads();

        #pragma unroll
        for (int k = 0; k < 16; k++) {
            float4 a4 = *(float4*)&sW[k][ty * 4];
            float4 x4 = *(float4*)&sX[k][tx * 4];
            float av[4] = {a4.x, a4.y, a4.z, a4.w};
            float xv[4] = {x4.x, x4.y, x4.z, x4.w};
            #pragma unroll
            for (int i = 0; i < 4; i++)
                #pragma unroll
                for (int j = 0; j < 4; j++)
                    acc[i][j] += av[i] * xv[j];
        }
        __syncthreads();
    }

    #pragma unroll
    for (int i = 0; i < 4; i++) {
        float bi = bias[o0 + ty * 4 + i];
        float4 r = make_float4(acc[i][0] + bi, acc[i][1] + bi,
                               acc[i][2] + bi, acc[i][3] + bi);
        *(float4*)&out[(size_t)(b * Cc + o0 + ty * 4 + i) * L + l0 + tx * 4] = r;
    }
}

// ---------------------------------------------------------------------------
// Flash attention (fp32) for one (b, h, 64-query tile).
// Q tile smem-resident; loop over 64-wide K/V tiles.
//   S = (Q^T K) / 8   -> online softmax -> O += P V^T
// Thread layout 16x16, 4x4 microtiles.
// grid: (Nn/64, Hh, Bb), 256 threads, dynamic smem.
// ---------------------------------------------------------------------------
__global__ __launch_bounds__(256) void attn_kernel(
    const float* __restrict__ Qg, const float* __restrict__ Kg,
    const float* __restrict__ Vg, float* __restrict__ Og)
{
    extern __shared__ float sm[];
    float* Qs   = sm;                 // [d][n]  64x64
    float* Ks   = Qs + 64 * 64;       // [d][m]  64x64
    float* Vs   = Ks + 64 * 64;       // [m][d]  64xPT
    float* Pt   = Vs + 64 * PT;       // [m][n]  64xPT
    float* mrow = Pt + 64 * PT;       // [64] running max
    float* lrow = mrow + 64;          // [64] running sum
    float* arow = lrow + 64;          // [64] rescale factor

    const int tid = threadIdx.x;
    const int n0 = blockIdx.x * 64;
    const int h = blockIdx.y, b = blockIdx.z;
    const size_t hb = (size_t)(b * Cc + h * Dd);
    const float* Qh = Qg + hb * Nn;
    const float* Kh = Kg + hb * Mm;
    const float* Vh = Vg + hb * Mm;
    float* Oh = Og + hb * Nn;

    const int r = tid >> 4;              // 0..15
    const int c4 = (tid & 15) * 4;       // 0,4,..,60

    // Load Q tile: Qs[d][n]
    #pragma unroll
    for (int i = 0; i < 4; i++) {
        int d = r + i * 16;
        *(float4*)&Qs[d * 64 + c4] = *(const float4*)&Qh[(size_t)d * Nn + n0 + c4];
    }
    if (tid < 64) { mrow[tid] = -1e30f; lrow[tid] = 0.f; }

    const int ty = tid >> 4, tx = tid & 15;
    float oacc[4][4] = {};   // [i over d=ty*4+i][j over n=tx*4+j]

    for (int mt = 0; mt < Mm; mt += 64) {
        // Load K tile [d][m] and V tile transposed [m][d]
        #pragma unroll
        for (int i = 0; i < 4; i++) {
            int d = r + i * 16;
            *(float4*)&Ks[d * 64 + c4] =
                *(const float4*)&Kh[(size_t)d * Mm + mt + c4];
            float4 v4 = *(const float4*)&Vh[(size_t)d * Mm + mt + c4];
            Vs[(c4 + 0) * PT + d] = v4.x;
            Vs[(c4 + 1) * PT + d] = v4.y;
            Vs[(c4 + 2) * PT + d] = v4.z;
            Vs[(c4 + 3) * PT + d] = v4.w;
        }
        __syncthreads();

        // Stage A: S[n][m] (n = ty*4+i, m = tx*4+j)
        float s[4][4] = {};
        #pragma unroll 16
        for (int d = 0; d < 64; d++) {
            float4 q4 = *(float4*)&Qs[d * 64 + ty * 4];
            float4 k4 = *(float4*)&Ks[d * 64 + tx * 4];
            float qv[4] = {q4.x, q4.y, q4.z, q4.w};
            float kv[4] = {k4.x, k4.y, k4.z, k4.w};
            #pragma unroll
            for (int i = 0; i < 4; i++)
                #pragma unroll
                for (int j = 0; j < 4; j++)
                    s[i][j] += qv[i] * kv[j];
        }
        // store scaled S transposed: Pt[m][n]
        #pragma unroll
        for (int j = 0; j < 4; j++) {
            float4 v = make_float4(s[0][j] * 0.125f, s[1][j] * 0.125f,
                                   s[2][j] * 0.125f, s[3][j] * 0.125f);
            *(float4*)&Pt[(tx * 4 + j) * PT + ty * 4] = v;
        }
        __syncthreads();

        // Stage B: online softmax over the 64 columns of each query row.
        // 4 threads per row (row n = tid>>2, part = tid&3 scans 16 m's).
        {
            const int n = tid >> 2, part = tid & 3;
            const int base = part * 16;
            float mloc = -1e30f;
            #pragma unroll
            for (int s2 = 0; s2 < 16; s2++)
                mloc = fmaxf(mloc, Pt[(base + s2) * PT + n]);
            mloc = fmaxf(mloc, __shfl_xor_sync(0xffffffffu, mloc, 1));
            mloc = fmaxf(mloc, __shfl_xor_sync(0xffffffffu, mloc, 2));
            float mprev = mrow[n];
            float mnew = fmaxf(mprev, mloc);
            float sum = 0.f;
            #pragma unroll
            for (int s2 = 0; s2 < 16; s2++) {
                int idx = (base + s2) * PT + n;
                float e = __expf(Pt[idx] - mnew);
                Pt[idx] = e;
                sum += e;
            }
            sum += __shfl_xor_sync(0xffffffffu, sum, 1);
            sum += __shfl_xor_sync(0xffffffffu, sum, 2);
            if (part == 0) {
                float a = __expf(mprev - mnew);
                arow[n] = a;
                lrow[n] = lrow[n] * a + sum;
                mrow[n] = mnew;
            }
        }
        __syncthreads();

        // Stage C: rescale O and accumulate O[d][n] += sum_m P[m][n]*V[m][d]
        {
            float4 al = *(float4*)&arow[tx * 4];
            float av[4] = {al.x, al.y, al.z, al.w};
            #pragma unroll
            for (int i = 0; i < 4; i++)
                #pragma unroll
                for (int j = 0; j < 4; j++)
                    oacc[i][j] *= av[j];
            #pragma unroll 16
            for (int m = 0; m < 64; m++) {
                float4 p4 = *(float4*)&Pt[m * PT + tx * 4];
                float4 v4 = *(float4*)&Vs[m * PT + ty * 4];
                float pv[4] = {p4.x, p4.y, p4.z, p4.w};
                float vv[4] = {v4.x, v4.y, v4.z, v4.w};
                #pragma unroll
                for (int i = 0; i < 4; i++)
                    #pragma unroll
                    for (int j = 0; j < 4; j++)
                        oacc[i][j] += vv[i] * pv[j];
            }
        }
        __syncthreads();
    }

    // Epilogue: divide by l and store (coalesced: n fastest)
    {
        float4 l4 = *(float4*)&lrow[tx * 4];
        float inv[4] = {1.f / l4.x, 1.f / l4.y, 1.f / l4.z, 1.f / l4.w};
        #pragma unroll
        for (int i = 0; i < 4; i++) {
            int d = ty * 4 + i;
            float4 o = make_float4(oacc[i][0] * inv[0], oacc[i][1] * inv[1],
                                   oacc[i][2] * inv[2], oacc[i][3] * inv[3]);
            *(float4*)&Oh[(size_t)d * Nn + n0 + tx * 4] = o;
        }
    }
}

// ---------------------------------------------------------------------------
extern "C" void kernel_launch(void* const* d_in, const int* in_sizes, int n_in,
                              void* d_out, int out_size)
{
    const float* query  = (const float*)d_in[0];
    const float* source = (const float*)d_in[1];
    const float* Wq = (const float*)d_in[2];
    const float* bq = (const float*)d_in[3];
    const float* Wk = (const float*)d_in[4];
    const float* bk = (const float*)d_in[5];
    const float* Wv = (const float*)d_in[6];
    const float* bv = (const float*)d_in[7];
    const float* Wm = (const float*)d_in[8];
    const float* bm = (const float*)d_in[9];
    float* out = (float*)d_out;

    float *pQ, *pK, *pV, *pO;
    cudaGetSymbolAddress((void**)&pQ, g_Q);
    cudaGetSymbolAddress((void**)&pK, g_K);
    cudaGetSymbolAddress((void**)&pV, g_V);
    cudaGetSymbolAddress((void**)&pO, g_O);

    const int smem = (64 * 64 * 2 + 64 * PT * 2 + 192) * (int)sizeof(float);
    cudaFuncSetAttribute(attn_kernel,
                         cudaFuncAttributeMaxDynamicSharedMemorySize, smem);

    dim3 gq(Nn / 64, Cc / 64, Bb);
    dim3 gs(Mm / 64, Cc / 64, Bb);
    dim3 ga(Nn / 64, Hh, Bb);

    proj_kernel<<<gq, 256>>>(Wq, bq, query,  pQ, Nn);
    proj_kernel<<<gs, 256>>>(Wk, bk, source, pK, Mm);
    proj_kernel<<<gs, 256>>>(Wv, bv, source, pV, Mm);
    attn_kernel<<<ga, 256, smem>>>(pQ, pK, pV, pO);
    proj_kernel<<<gq, 256>>>(Wm, bm, pO, out, Nn);
}